// round 4
// baseline (speedup 1.0000x reference)
#include <cuda_runtime.h>
#include <cstdint>
#include <cstddef>

#define H 512
#define W 512
#define C 128
#define TI 16
#define TJ 16
// weights smem: [16 i][16 j][64 t], i-stride padded 1024 -> 1032 (== 8 mod 32)
#define WISTRIDE 1032
#define W3_FLOATS (16 * WISTRIDE)        // 16512
// x halo smem per pass: 32 channels as [16 chg][529 pix][2 ch]
#define XCHUNK 1058                      // 529*2; mod 32 == 2 -> 16 chgs spread banks
#define XBUF (16 * XCHUNK)               // 16928 floats per buffer
#define SMEM_FLOATS (W3_FLOATS + 2 * XBUF + 529 + 256)
#define SMEM_BYTES (SMEM_FLOATS * 4)     // 204,612 B

typedef unsigned long long ull;

__device__ __forceinline__ ull pack2(float a, float b) {
    ull r; asm("mov.b64 %0, {%1, %2};" : "=l"(r) : "f"(a), "f"(b)); return r;
}
__device__ __forceinline__ void fma2(ull& d, ull a, ull b) {
    asm("fma.rn.f32x2 %0, %1, %2, %0;" : "+l"(d) : "l"(a), "l"(b));
}
__device__ __forceinline__ float2 unpack2(ull v) {
    float2 f; asm("mov.b64 {%0, %1}, %2;" : "=f"(f.x), "=f"(f.y) : "l"(v)); return f;
}
__device__ __forceinline__ void cp_async16(float* smem_dst, const float* gsrc, bool pred) {
    uint32_t s = (uint32_t)__cvta_generic_to_shared(smem_dst);
    int sz = pred ? 16 : 0;
    asm volatile("cp.async.cg.shared.global [%0], [%1], 16, %2;\n"
                 :: "r"(s), "l"(gsrc), "r"(sz));
}
__device__ __forceinline__ void cp_async8(float* smem_dst, const float* gsrc, bool pred) {
    uint32_t s = (uint32_t)__cvta_generic_to_shared(smem_dst);
    int sz = pred ? 8 : 0;
    asm volatile("cp.async.ca.shared.global [%0], [%1], 8, %2;\n"
                 :: "r"(s), "l"(gsrc), "r"(sz));
}
__device__ __forceinline__ void cp_async4(float* smem_dst, const float* gsrc, bool pred) {
    uint32_t s = (uint32_t)__cvta_generic_to_shared(smem_dst);
    int sz = pred ? 4 : 0;
    asm volatile("cp.async.ca.shared.global [%0], [%1], 4, %2;\n"
                 :: "r"(s), "l"(gsrc), "r"(sz));
}
__device__ __forceinline__ void cp_commit() {
    asm volatile("cp.async.commit_group;\n" ::: "memory");
}
template <int N> __device__ __forceinline__ void cp_wait() {
    asm volatile("cp.async.wait_group %0;\n" :: "n"(N) : "memory");
}

// ---- stage one 32-channel x halo pass into xbuf[16 chg][529 pix][2] ----
// 16 consecutive lanes cover one pixel's 32 channels (128 B contiguous gmem).
__device__ __forceinline__ void stage_x(float* xbuf, const float* __restrict__ gx,
                                        int bi, int bj, int pass, int tid) {
    const int cbase = pass * 32;
    #pragma unroll 4
    for (int u = tid; u < 529 * 16; u += 512) {
        int q = u & 15, pix = u >> 4;
        int hr = pix / 23, hc = pix - hr * 23;
        int gr = bi + hr - 3, gcl = bj + hc - 3;
        bool ok = ((unsigned)gr < H) && ((unsigned)gcl < W);
        const float* src = ok
            ? gx + (((size_t)gr * W + gcl) * C + cbase + q * 2)
            : gx;
        cp_async8(xbuf + q * XCHUNK + pix * 2, src, ok);
    }
}

// ---- compute one pass: 1 row x 8 cols x 2 ch per thread ----
__device__ __forceinline__ void compute_pass(const float* __restrict__ xbuf,
                                             const float* __restrict__ w3,
                                             const float* __restrict__ inv,
                                             float* __restrict__ gout,
                                             int bi, int bj, int cbase,
                                             int row, int j0, int chg) {
    ull acc[8];
    #pragma unroll
    for (int j = 0; j < 8; ++j) acc[j] = 0ull;

    const float* xb   = xbuf + chg * XCHUNK;
    const float* wrow = w3 + row * WISTRIDE + j0 * 64;

    #pragma unroll
    for (int p = 0; p < 8; ++p) {
        // load the 15-position halo row (2 ch each) into registers
        ull xv[15];
        const float* xr = xb + ((row + p) * 23 + j0) * 2;
        #pragma unroll
        for (int t = 0; t < 15; ++t)
            xv[t] = *(const ull*)(xr + t * 2);

        #pragma unroll
        for (int j = 0; j < 8; ++j) {
            #pragma unroll
            for (int qg = 0; qg < 2; ++qg) {
                float4 w4 = *(const float4*)(wrow + j * 64 + p * 8 + qg * 4);
                const int q0 = qg * 4;
                fma2(acc[j], xv[j + q0 + 0], pack2(w4.x, w4.x));
                fma2(acc[j], xv[j + q0 + 1], pack2(w4.y, w4.y));
                fma2(acc[j], xv[j + q0 + 2], pack2(w4.z, w4.z));
                fma2(acc[j], xv[j + q0 + 3], pack2(w4.w, w4.w));
            }
        }
    }
    // normalize + store (per j: 2 rows x 16 chg x 8B = two 128B segments)
    #pragma unroll
    for (int j = 0; j < 8; ++j) {
        float s = inv[row * 16 + j0 + j];
        float2 a = unpack2(acc[j]);
        float2 v = make_float2(a.x * s, a.y * s);
        *(float2*)(gout + (((size_t)(bi + row) * W + (bj + j0 + j)) * C
                           + cbase + chg * 2)) = v;
    }
}

__global__ __launch_bounds__(512, 1) void cell_att_kernel(
    const float* __restrict__ gx,   // [H][W][C]
    const float* __restrict__ gw,   // [H][W][64]
    const float* __restrict__ gc,   // [H][W]
    float* __restrict__ gout)       // [H][W][C]
{
    extern __shared__ float smem[];
    float* w3  = smem;                 // [16 i][16 j][64 t], i-stride 1032
    float* xs0 = w3 + W3_FLOATS;
    float* xs1 = xs0 + XBUF;
    float* ch  = xs1 + XBUF;           // 23x23 cnts halo
    float* inv = ch + 529;             // 256 per-pixel 1/(tcnt+1e-6)

    const int tid = threadIdx.x;
    const int chg = tid & 15;          // channel pair within pass (2 ch)
    const int rem = tid >> 4;          // 0..31
    const int row = rem & 15;          // 0..15
    const int j0  = (rem >> 4) * 8;    // 0 or 8
    const int bi = blockIdx.y * TI, bj = blockIdx.x * TJ;

    // ---- G0: weights (coalesced, natural layout) + cnts halo ----
    #pragma unroll 8
    for (int u = tid; u < 256 * 16; u += 512) {
        int quad = u & 15, px = u >> 4;
        int il = px >> 4, jl = px & 15;
        const float* src = gw + ((size_t)(bi + il) * W + (bj + jl)) * 64 + quad * 4;
        cp_async16(w3 + il * WISTRIDE + jl * 64 + quad * 4, src, true);
    }
    for (int u = tid; u < 529; u += 512) {
        int hr = u / 23, hc = u - hr * 23;
        int gr = bi + hr - 3, gcl = bj + hc - 3;
        bool ok = ((unsigned)gr < H) && ((unsigned)gcl < W);
        const float* src = ok ? gc + (size_t)gr * W + gcl : gc;
        cp_async4(ch + u, src, ok);
    }
    cp_commit();                       // G0
    stage_x(xs0, gx, bi, bj, 0, tid);
    cp_commit();                       // G1
    stage_x(xs1, gx, bi, bj, 1, tid);
    cp_commit();                       // G2

    cp_wait<2>();                      // G0 (weights + cnts) done
    __syncthreads();

    // ---- normalizer: inv = 1/(att(cnts)+1e-6), one pixel per thread ----
    if (tid < 256) {
        int il = tid >> 4, jl = tid & 15;
        const float* wpx = w3 + il * WISTRIDE + jl * 64;
        float s = 0.f;
        #pragma unroll
        for (int p = 0; p < 8; ++p)
            #pragma unroll
            for (int q = 0; q < 8; ++q)
                s += ch[(il + p) * 23 + (jl + q)] * wpx[p * 8 + q];
        inv[tid] = 1.0f / (s + 1e-6f);
    }

    cp_wait<1>();                      // G1 (x pass0) done
    __syncthreads();                   // inv + x0 visible to all
    compute_pass(xs0, w3, inv, gout, bi, bj, 0, row, j0, chg);

    __syncthreads();                   // all readers done with xs0
    stage_x(xs0, gx, bi, bj, 2, tid);
    cp_commit();                       // G3
    cp_wait<1>();                      // G2 (x pass1) done
    __syncthreads();
    compute_pass(xs1, w3, inv, gout, bi, bj, 32, row, j0, chg);

    __syncthreads();                   // all readers done with xs1
    stage_x(xs1, gx, bi, bj, 3, tid);
    cp_commit();                       // G4
    cp_wait<1>();                      // G3 (x pass2) done
    __syncthreads();
    compute_pass(xs0, w3, inv, gout, bi, bj, 64, row, j0, chg);

    cp_wait<0>();                      // G4 (x pass3) done
    __syncthreads();
    compute_pass(xs1, w3, inv, gout, bi, bj, 96, row, j0, chg);
}

extern "C" void kernel_launch(void* const* d_in, const int* in_sizes, int n_in,
                              void* d_out, int out_size) {
    const float* x0 = (const float*)d_in[0];
    const float* w  = (const float*)d_in[1];
    const float* c  = (const float*)d_in[2];
    float* out      = (float*)d_out;
    cudaFuncSetAttribute(cell_att_kernel,
                         cudaFuncAttributeMaxDynamicSharedMemorySize, SMEM_BYTES);
    dim3 grid(W / TJ, H / TI);
    cell_att_kernel<<<grid, 512, SMEM_BYTES>>>(x0, w, c, out);
}